// round 1
// baseline (speedup 1.0000x reference)
#include <cuda_runtime.h>

// Problem constants (shape-derived at launch where possible)
#define NRK 4
#define DW  64
#define KD  (NRK * DW)   // 256 = stride of the (k,d) plane
#define PAD 2048         // power-of-2 padding for bitonic sort (Nt=1500 <= 2048)
#define THREADS 256

// Scratch accumulators (device globals; no allocation allowed)
__device__ double g_pair[NRK];
__device__ double g_alm[NRK];

__global__ void init_kernel() {
    int t = threadIdx.x;
    if (t < NRK) { g_pair[t] = 0.0; g_alm[t] = 0.0; }
}

// One block per (k,d) coordinate: blockIdx.x == k*64 + d == flat offset in the
// [NR, D] plane. Computes sum_{i,j} |s[i,k,d] - t[j,k,d]| exactly via
// sort + prefix-sum + binary search, accumulates into g_pair[k].
__global__ void __launch_bounds__(THREADS) pairsum_kernel(
    const float* __restrict__ s, const float* __restrict__ t,
    int Ns, int Nt)
{
    __shared__ float  ysort[PAD];
    __shared__ float  ypre[PAD];
    __shared__ float  aux[THREADS];
    __shared__ double red[THREADS];

    const int b   = blockIdx.x;   // k*64 + d
    const int tid = threadIdx.x;
    const float INF = __int_as_float(0x7f800000);

    // Load y = t[:, k, d] (stride KD floats), pad with +inf
    for (int j = tid; j < PAD; j += THREADS)
        ysort[j] = (j < Nt) ? t[j * KD + b] : INF;
    __syncthreads();

    // Bitonic sort ascending (pads float to the top)
    for (int k = 2; k <= PAD; k <<= 1) {
        for (int j = k >> 1; j > 0; j >>= 1) {
            #pragma unroll
            for (int ii = 0; ii < PAD / THREADS; ii++) {
                int i = tid + ii * THREADS;
                int ixj = i ^ j;
                if (ixj > i) {
                    float a = ysort[i], c = ysort[ixj];
                    bool up = ((i & k) == 0);
                    if ((a > c) == up) { ysort[i] = c; ysort[ixj] = a; }
                }
            }
            __syncthreads();
        }
    }

    // Inclusive scan of sorted y over first Nt entries (pads -> 0).
    // Blocked scan: 8 sequential per thread + serial scan of 256 partials.
    const int per = PAD / THREADS;  // 8
    {
        float run = 0.f;
        int base = tid * per;
        #pragma unroll
        for (int m = 0; m < per; m++) {
            int idx = base + m;
            float v = (idx < Nt) ? ysort[idx] : 0.f;
            run += v;
            ypre[idx] = run;
        }
        aux[tid] = run;
    }
    __syncthreads();
    if (tid == 0) {
        float run = 0.f;
        for (int i = 0; i < THREADS; i++) { float v = aux[i]; aux[i] = run; run += v; }
    }
    __syncthreads();
    {
        float off = aux[tid];
        int base = tid * per;
        #pragma unroll
        for (int m = 0; m < per; m++) ypre[base + m] += off;
    }
    __syncthreads();

    const float Ptot = ypre[Nt - 1];

    // For each x = s[i,k,d]: c = #{y <= x}; contribution is exact L1 pair sum.
    double acc = 0.0;
    for (int i = tid; i < Ns; i += THREADS) {
        float x = s[i * KD + b];
        int lo = 0, hi = Nt;
        while (lo < hi) {
            int mid = (lo + hi) >> 1;
            if (ysort[mid] <= x) lo = mid + 1; else hi = mid;
        }
        int c = lo;
        float Pc = (c > 0) ? ypre[c - 1] : 0.f;
        float contrib = x * (float)(2 * c - Nt) + Ptot - 2.f * Pc;
        acc += (double)contrib;
    }

    red[tid] = acc;
    __syncthreads();
    for (int st = THREADS / 2; st > 0; st >>= 1) {
        if (tid < st) red[tid] += red[tid + st];
        __syncthreads();
    }
    if (tid == 0) atomicAdd(&g_pair[b >> 6], red[0]);
}

// Anchor-pair L1 sums per k. One block, 256 threads; thread tid owns the fixed
// plane coordinate (k,d) = (tid/64, tid%64) and loops over anchors.
// Detects int64 vs int32 index dtype at runtime (JAX x64 ambiguity):
// anchor_rows are small ints, so int64 storage has zero odd 32-bit words.
__global__ void __launch_bounds__(256) alm_kernel(
    const float* __restrict__ s, const float* __restrict__ t,
    const void* __restrict__ rows_raw, const void* __restrict__ cols_raw,
    int nb)
{
    __shared__ int is64;
    __shared__ double red[256];
    const int tid = threadIdx.x;

    if (tid == 0) {
        const int* r32 = (const int*)rows_raw;
        is64 = (r32[1] == 0 && r32[3] == 0 && r32[5] == 0) ? 1 : 0;
    }
    __syncthreads();

    const long long* r64 = (const long long*)rows_raw;
    const long long* c64 = (const long long*)cols_raw;
    const int* r32 = (const int*)rows_raw;
    const int* c32 = (const int*)cols_raw;

    double acc = 0.0;
    for (int bi = 0; bi < nb; bi++) {
        long long r = is64 ? r64[bi] : (long long)r32[bi];
        long long c = is64 ? c64[bi] : (long long)c32[bi];
        float d = s[r * KD + tid] - t[c * KD + tid];
        acc += (double)fabsf(d);
    }
    red[tid] = acc;
    __syncthreads();
    // Reduce within each group of 64 threads (one group per k)
    for (int st = 32; st > 0; st >>= 1) {
        if ((tid & 63) < st) red[tid] += red[tid + st];
        __syncthreads();
    }
    if ((tid & 63) == 0) g_alm[tid >> 6] = red[tid];
}

__global__ void final_kernel(float* out, int Ns, int Nt, int nbB) {
    if (threadIdx.x == 0 && blockIdx.x == 0) {
        const double params[NRK] = {0.4, 0.2, 0.2, 0.2};
        const double EPS = 3.0;
        double nb_notB = (double)Ns * (double)Nt - (double)nbB;
        double ret = 0.0;
        #pragma unroll
        for (int k = 0; k < NRK; k++) {
            double all  = g_pair[k];
            double alm  = g_alm[k];
            double notalm = all - alm;
            double lk = alm * nb_notB + (EPS * nb_notB - notalm) * (double)nbB;
            ret += params[k] * lk / (double)DW;
        }
        out[0] = (float)(ret / ((double)Ns * (double)Nt));
    }
}

extern "C" void kernel_launch(void* const* d_in, const int* in_sizes, int n_in,
                              void* d_out, int out_size) {
    const float* s = (const float*)d_in[0];
    const float* t = (const float*)d_in[1];
    const void* rows = d_in[2];
    const void* cols = d_in[3];
    int Ns = in_sizes[0] / KD;
    int Nt = in_sizes[1] / KD;
    int nb = in_sizes[2];

    init_kernel<<<1, 32>>>();
    pairsum_kernel<<<KD, THREADS>>>(s, t, Ns, Nt);
    alm_kernel<<<1, 256>>>(s, t, rows, cols, nb);
    final_kernel<<<1, 32>>>((float*)d_out, Ns, Nt, nb);
}

// round 2
// speedup vs baseline: 1.9713x; 1.9713x over previous
#include <cuda_runtime.h>

#define NRK 4
#define DW  64
#define KD  (NRK * DW)   // 256
#define PAD 2048         // power-of-2 pad for bitonic (Nt=1500 <= 2048)
#define THREADS 256
#define PER 8            // elements per thread (PAD/THREADS)
#define ALM_BLOCKS 8

__device__ double g_pair[NRK];
__device__ double g_alm[NRK];

__global__ void init_kernel() {
    int t = threadIdx.x;
    if (t < NRK) { g_pair[t] = 0.0; g_alm[t] = 0.0; }
}

__device__ __forceinline__ void cmpswap(float& a, float& b, bool up) {
    float mn = fminf(a, b), mx = fmaxf(a, b);
    a = up ? mn : mx;
    b = up ? mx : mn;
}

// Blocks [0, KD): one per (k,d) plane coordinate. Exact all-pairs L1 via
// register+smem bitonic sort, shfl prefix scan, per-x binary search.
// Blocks [KD, KD+ALM_BLOCKS): anchor-pair L1 sums (parallelized over anchors).
__global__ void __launch_bounds__(THREADS) fused_kernel(
    const float* __restrict__ s, const float* __restrict__ t,
    const void* __restrict__ rows_raw, const void* __restrict__ cols_raw,
    int Ns, int Nt, int nb)
{
    const int tid  = threadIdx.x;
    const int lane = tid & 31;
    const int wid  = tid >> 5;

    if (blockIdx.x >= KD) {
        // ---- ALM part: thread tid owns plane coord tid, loops its anchor slice ----
        __shared__ int is64;
        if (tid == 0) {
            const int* r32 = (const int*)rows_raw;
            // rows are small ints (arange): int64 storage has zero odd words
            is64 = (r32[1] == 0 && r32[3] == 0 && r32[5] == 0) ? 1 : 0;
        }
        __syncthreads();
        int a = blockIdx.x - KD;
        int chunk = (nb + ALM_BLOCKS - 1) / ALM_BLOCKS;
        int lo = a * chunk, hi = min(nb, lo + chunk);
        const long long* r64 = (const long long*)rows_raw;
        const long long* c64 = (const long long*)cols_raw;
        const int* r32 = (const int*)rows_raw;
        const int* c32 = (const int*)cols_raw;
        double acc = 0.0;
        for (int bi = lo; bi < hi; bi++) {
            long long r = is64 ? r64[bi] : (long long)r32[bi];
            long long c = is64 ? c64[bi] : (long long)c32[bi];
            acc += (double)fabsf(s[r * KD + tid] - t[c * KD + tid]);
        }
        #pragma unroll
        for (int o = 16; o > 0; o >>= 1) acc += __shfl_down_sync(0xffffffffu, acc, o);
        if (lane == 0) atomicAdd(&g_alm[tid >> 6], acc);
        return;
    }

    __shared__ float  ysort[PAD];
    __shared__ float  ypre[PAD];
    __shared__ float  warpsum[8];
    __shared__ double dred[8];

    const int b = blockIdx.x;     // k*64 + d
    const float INF = __int_as_float(0x7f800000);

    for (int j = tid; j < PAD; j += THREADS)
        ysort[j] = (j < Nt) ? t[j * KD + b] : INF;
    __syncthreads();

    const int base = tid * PER;

    // ---- phases k=2,4,8 fully in registers: sort own 8-chunk, dir by parity ----
    {
        float v[PER];
        #pragma unroll
        for (int m = 0; m < PER; m++) v[m] = ysort[base + m];
        bool asc = ((tid & 1) == 0);
        #pragma unroll
        for (int kk = 2; kk <= 8; kk <<= 1) {
            #pragma unroll
            for (int j = kk >> 1; j > 0; j >>= 1) {
                #pragma unroll
                for (int m = 0; m < PER; m++)
                    if ((m & j) == 0) {
                        bool up = (kk == 8) ? asc : ((m & kk) == 0);
                        cmpswap(v[m], v[m | j], up);
                    }
            }
        }
        #pragma unroll
        for (int m = 0; m < PER; m++) ysort[base + m] = v[m];
    }
    __syncthreads();

    // ---- phases k=16..2048: smem steps j=k/2..8 (pair-indexed, all threads
    //      active), then j=4,2,1 finished in registers ----
    for (int k = 16; k <= PAD; k <<= 1) {
        for (int j = k >> 1; j >= PER; j >>= 1) {
            #pragma unroll
            for (int w = 0; w < PAD / 2 / THREADS; w++) {
                int p = tid + w * THREADS;
                int i = ((p & ~(j - 1)) << 1) | (p & (j - 1));
                int q = i | j;
                bool up = ((i & k) == 0);
                float a = ysort[i], c = ysort[q];
                float mn = fminf(a, c), mx = fmaxf(a, c);
                ysort[i] = up ? mn : mx;
                ysort[q] = up ? mx : mn;
            }
            __syncthreads();
        }
        {
            float v[PER];
            #pragma unroll
            for (int m = 0; m < PER; m++) v[m] = ysort[base + m];
            bool up = ((base & k) == 0);
            #pragma unroll
            for (int j = 4; j > 0; j >>= 1) {
                #pragma unroll
                for (int m = 0; m < PER; m++)
                    if ((m & j) == 0) cmpswap(v[m], v[m | j], up);
            }
            #pragma unroll
            for (int m = 0; m < PER; m++) ysort[base + m] = v[m];
        }
        __syncthreads();
    }

    // ---- inclusive prefix scan of sorted y (pads -> 0): regs + shfl ----
    {
        float pre[PER];
        float run = 0.f;
        #pragma unroll
        for (int m = 0; m < PER; m++) {
            float x = (base + m < Nt) ? ysort[base + m] : 0.f;
            run += x;
            pre[m] = run;
        }
        float incl = run;
        #pragma unroll
        for (int o = 1; o < 32; o <<= 1) {
            float n = __shfl_up_sync(0xffffffffu, incl, o);
            if (lane >= o) incl += n;
        }
        if (lane == 31) warpsum[wid] = incl;
        float excl = incl - run;
        __syncthreads();
        float woff = 0.f;
        #pragma unroll
        for (int w = 0; w < 8; w++)
            if (w < wid) woff += warpsum[w];
        float off = woff + excl;
        #pragma unroll
        for (int m = 0; m < PER; m++) ypre[base + m] = pre[m] + off;
    }
    __syncthreads();

    const float Ptot = ypre[Nt - 1];

    // ---- per-x binary search + exact contribution ----
    double acc = 0.0;
    for (int i = tid; i < Ns; i += THREADS) {
        float x = s[i * KD + b];
        int lo = 0, hi = Nt;
        while (lo < hi) {
            int mid = (lo + hi) >> 1;
            if (ysort[mid] <= x) lo = mid + 1; else hi = mid;
        }
        float Pc = (lo > 0) ? ypre[lo - 1] : 0.f;
        acc += (double)(x * (float)(2 * lo - Nt) + Ptot - 2.f * Pc);
    }
    #pragma unroll
    for (int o = 16; o > 0; o >>= 1) acc += __shfl_down_sync(0xffffffffu, acc, o);
    if (lane == 0) dred[wid] = acc;
    __syncthreads();
    if (tid == 0) {
        double sum = 0.0;
        #pragma unroll
        for (int w = 0; w < 8; w++) sum += dred[w];
        atomicAdd(&g_pair[b >> 6], sum);
    }
}

__global__ void final_kernel(float* out, int Ns, int Nt, int nbB) {
    if (threadIdx.x == 0 && blockIdx.x == 0) {
        const double params[NRK] = {0.4, 0.2, 0.2, 0.2};
        const double EPS = 3.0;
        double nb_notB = (double)Ns * (double)Nt - (double)nbB;
        double ret = 0.0;
        #pragma unroll
        for (int k = 0; k < NRK; k++) {
            double all    = g_pair[k];
            double alm    = g_alm[k];
            double notalm = all - alm;
            double lk = alm * nb_notB + (EPS * nb_notB - notalm) * (double)nbB;
            ret += params[k] * lk / (double)DW;
        }
        out[0] = (float)(ret / ((double)Ns * (double)Nt));
    }
}

extern "C" void kernel_launch(void* const* d_in, const int* in_sizes, int n_in,
                              void* d_out, int out_size) {
    const float* s = (const float*)d_in[0];
    const float* t = (const float*)d_in[1];
    const void* rows = d_in[2];
    const void* cols = d_in[3];
    int Ns = in_sizes[0] / KD;
    int Nt = in_sizes[1] / KD;
    int nb = in_sizes[2];

    init_kernel<<<1, 32>>>();
    fused_kernel<<<KD + ALM_BLOCKS, THREADS>>>(s, t, rows, cols, Ns, Nt, nb);
    final_kernel<<<1, 32>>>((float*)d_out, Ns, Nt, nb);
}

// round 3
// speedup vs baseline: 3.3876x; 1.7184x over previous
#include <cuda_runtime.h>

#define NRK 4
#define DW  64
#define KD  256          // NR*D plane stride
#define PAD 2048         // power-of-2 pad for bitonic (Nt <= 2048)
#define THREADS 256
#define PER 8            // elements per thread
#define ALM_BLOCKS 8
#define NMAX 2048
#define TOTAL_BLOCKS (KD + ALM_BLOCKS)

// Static scratch (no allocation allowed)
__device__ float  g_sT[KD * NMAX];          // s transposed: [KD][Ns]
__device__ float  g_tT[KD * NMAX];          // t transposed: [KD][Nt]
__device__ double g_col[KD];                // per-column all-pairs partial
__device__ double g_almp[ALM_BLOCKS * NRK]; // per-block per-k anchor partials
__device__ int    g_count = 0;              // completion ticket (self-resetting)

// ---------------- tiled transpose: [N][256] -> [256][N] ----------------
__global__ void transpose_kernel(const float* __restrict__ s,
                                 const float* __restrict__ t,
                                 int Ns, int Nt) {
    __shared__ float tile[32][33];
    const float* src; float* dst; int N;
    if (blockIdx.z == 0) { src = s; dst = g_sT; N = Ns; }
    else                 { src = t; dst = g_tT; N = Nt; }
    const int tx = threadIdx.x, ty = threadIdx.y;  // 32 x 8
    const int r0 = blockIdx.x * 32, c0 = blockIdx.y * 32;
    #pragma unroll
    for (int i = 0; i < 4; i++) {
        int r = r0 + ty + i * 8;
        if (r < N) tile[ty + i * 8][tx] = src[r * KD + c0 + tx];
    }
    __syncthreads();
    #pragma unroll
    for (int i = 0; i < 4; i++) {
        int c  = c0 + ty + i * 8;   // KD-dim row of dst
        int rr = r0 + tx;           // N-dim col
        if (rr < N) dst[c * N + rr] = tile[tx][ty + i * 8];
    }
}

__device__ __forceinline__ void cmpswap(float& a, float& b, bool up) {
    float mn = fminf(a, b), mx = fmaxf(a, b);
    a = up ? mn : mx;
    b = up ? mx : mn;
}

// ---------------- fused: column pair-sums + ALM + finalize ----------------
__global__ void __launch_bounds__(THREADS) fused_kernel(
    const float* __restrict__ s, const float* __restrict__ t,
    const void* __restrict__ rows_raw, const void* __restrict__ cols_raw,
    float* __restrict__ out, int Ns, int Nt, int nb)
{
    __shared__ float  ysort[PAD];
    __shared__ float  ypre[PAD];
    __shared__ float  fwarp[8];
    __shared__ double dwarp[8];
    __shared__ int    slast;

    const int tid  = threadIdx.x;
    const int lane = tid & 31;
    const int wid  = tid >> 5;
    const int b    = blockIdx.x;

    if (b >= KD) {
        // ======== ALM blocks: anchor-pair L1 sums, sliced over anchors ========
        __shared__ int is64;
        if (tid == 0) {
            const int* r32 = (const int*)rows_raw;
            is64 = (r32[1] == 0 && r32[3] == 0 && r32[5] == 0) ? 1 : 0;
        }
        __syncthreads();
        const int a = b - KD;
        const int chunk = (nb + ALM_BLOCKS - 1) / ALM_BLOCKS;
        const int lo = a * chunk, hi = min(nb, lo + chunk);
        const long long* r64 = (const long long*)rows_raw;
        const long long* c64 = (const long long*)cols_raw;
        const int* r32 = (const int*)rows_raw;
        const int* c32 = (const int*)cols_raw;
        double acc = 0.0;
        for (int bi = lo; bi < hi; bi++) {
            long long r = is64 ? r64[bi] : (long long)r32[bi];
            long long c = is64 ? c64[bi] : (long long)c32[bi];
            acc += (double)fabsf(s[r * KD + tid] - t[c * KD + tid]);
        }
        #pragma unroll
        for (int o = 16; o > 0; o >>= 1) acc += __shfl_down_sync(0xffffffffu, acc, o);
        if (lane == 0) dwarp[wid] = acc;
        __syncthreads();
        if (tid == 0) {
            #pragma unroll
            for (int k = 0; k < NRK; k++)
                g_almp[a * NRK + k] = dwarp[2 * k] + dwarp[2 * k + 1];
        }
    } else {
        // ======== column blocks: exact all-pairs L1 for plane coord b ========
        const float INF = __int_as_float(0x7f800000);
        const float* ycol = g_tT + (size_t)b * Nt;
        const float* xcol = g_sT + (size_t)b * Ns;
        const int base = tid * PER;

        float v[PER];
        #pragma unroll
        for (int m = 0; m < PER; m++)
            v[m] = (base + m < Nt) ? ycol[base + m] : INF;

        // --- phases k=2,4,8: sort own 8-chunk in registers ---
        {
            const bool asc = ((tid & 1) == 0);
            #pragma unroll
            for (int kk = 2; kk <= 8; kk <<= 1) {
                #pragma unroll
                for (int j = kk >> 1; j > 0; j >>= 1) {
                    #pragma unroll
                    for (int m = 0; m < PER; m++)
                        if ((m & j) == 0) {
                            bool up = (kk == 8) ? asc : ((m & kk) == 0);
                            cmpswap(v[m], v[m | j], up);
                        }
                }
            }
        }

        // --- phases k=16..2048: smem only for j>=256, shfl for j=128..8 ---
        float4* sh4 = (float4*)ysort;
        #pragma unroll
        for (int k = 16; k <= PAD; k <<= 1) {
            const bool up = ((tid & (k >> 3)) == 0);
            // cross-warp steps via smem (conflict-free float4)
            #pragma unroll
            for (int j = k >> 1; j >= 256; j >>= 1) {
                const int jd = j >> 3;
                sh4[tid * 2 + 0] = make_float4(v[0], v[1], v[2], v[3]);
                sh4[tid * 2 + 1] = make_float4(v[4], v[5], v[6], v[7]);
                __syncthreads();
                const int p = tid ^ jd;
                float4 oa = sh4[p * 2 + 0], ob = sh4[p * 2 + 1];
                float o[PER] = {oa.x, oa.y, oa.z, oa.w, ob.x, ob.y, ob.z, ob.w};
                const bool keep_min = (((tid & jd) == 0) == up);
                #pragma unroll
                for (int m = 0; m < PER; m++)
                    v[m] = keep_min ? fminf(v[m], o[m]) : fmaxf(v[m], o[m]);
                __syncthreads();
            }
            // intra-warp steps via shfl
            #pragma unroll
            for (int j = ((k >> 1) < 128 ? (k >> 1) : 128); j >= 8; j >>= 1) {
                const int jd = j >> 3;
                const bool keep_min = (((tid & jd) == 0) == up);
                #pragma unroll
                for (int m = 0; m < PER; m++) {
                    float o = __shfl_xor_sync(0xffffffffu, v[m], jd);
                    v[m] = keep_min ? fminf(v[m], o) : fmaxf(v[m], o);
                }
            }
            // intra-thread steps j=4,2,1
            #pragma unroll
            for (int j = 4; j > 0; j >>= 1) {
                #pragma unroll
                for (int m = 0; m < PER; m++)
                    if ((m & j) == 0) cmpswap(v[m], v[m | j], up);
            }
        }

        // --- inclusive prefix scan (pads -> 0), regs + shfl ---
        float pre[PER];
        {
            float run = 0.f;
            #pragma unroll
            for (int m = 0; m < PER; m++) {
                float x = (base + m < Nt) ? v[m] : 0.f;
                run += x;
                pre[m] = run;
            }
            float incl = run;
            #pragma unroll
            for (int o = 1; o < 32; o <<= 1) {
                float n = __shfl_up_sync(0xffffffffu, incl, o);
                if (lane >= o) incl += n;
            }
            if (lane == 31) fwarp[wid] = incl;
            const float excl = incl - run;
            __syncthreads();
            float woff = 0.f;
            #pragma unroll
            for (int w = 0; w < 8; w++)
                if (w < wid) woff += fwarp[w];
            const float off = woff + excl;
            #pragma unroll
            for (int m = 0; m < PER; m++) pre[m] += off;
        }

        // publish sorted values + prefix sums to smem
        __syncthreads();  // sh4 (ysort) reuse safety
        sh4[tid * 2 + 0] = make_float4(v[0], v[1], v[2], v[3]);
        sh4[tid * 2 + 1] = make_float4(v[4], v[5], v[6], v[7]);
        float4* pre4 = (float4*)ypre;
        pre4[tid * 2 + 0] = make_float4(pre[0], pre[1], pre[2], pre[3]);
        pre4[tid * 2 + 1] = make_float4(pre[4], pre[5], pre[6], pre[7]);
        __syncthreads();

        const float Ptot = ypre[Nt - 1];

        // --- per-x binary search + exact contribution ---
        double acc = 0.0;
        for (int i = tid; i < Ns; i += THREADS) {
            const float x = xcol[i];
            int lo = 0, hi = Nt;
            while (lo < hi) {
                int mid = (lo + hi) >> 1;
                if (ysort[mid] <= x) lo = mid + 1; else hi = mid;
            }
            float Pc = (lo > 0) ? ypre[lo - 1] : 0.f;
            acc += (double)(x * (float)(2 * lo - Nt) + Ptot - 2.f * Pc);
        }
        #pragma unroll
        for (int o = 16; o > 0; o >>= 1) acc += __shfl_down_sync(0xffffffffu, acc, o);
        if (lane == 0) dwarp[wid] = acc;
        __syncthreads();
        if (tid == 0) {
            double sum = 0.0;
            #pragma unroll
            for (int w = 0; w < 8; w++) sum += dwarp[w];
            g_col[b] = sum;
        }
    }

    // ======== completion ticket: last block finalizes ========
    if (tid == 0) {
        __threadfence();
        int tk = atomicAdd(&g_count, 1);
        slast = (tk == TOTAL_BLOCKS - 1) ? 1 : 0;
    }
    __syncthreads();
    if (!slast) return;
    __threadfence();

    // reduce g_col (256 doubles) by k-groups of 64
    double vv = g_col[tid];
    #pragma unroll
    for (int o = 16; o > 0; o >>= 1) vv += __shfl_down_sync(0xffffffffu, vv, o);
    if (lane == 0) dwarp[wid] = vv;
    __syncthreads();
    if (tid == 0) {
        const double params[NRK] = {0.4, 0.2, 0.2, 0.2};
        const double EPS = 3.0;
        const double nb_notB = (double)Ns * (double)Nt - (double)nb;
        double ret = 0.0;
        #pragma unroll
        for (int k = 0; k < NRK; k++) {
            double all = dwarp[2 * k] + dwarp[2 * k + 1];
            double alm = 0.0;
            #pragma unroll
            for (int a = 0; a < ALM_BLOCKS; a++) alm += g_almp[a * NRK + k];
            double notalm = all - alm;
            double lk = alm * nb_notB + (EPS * nb_notB - notalm) * (double)nb;
            ret += params[k] * lk / (double)DW;
        }
        out[0] = (float)(ret / ((double)Ns * (double)Nt));
        g_count = 0;  // reset for next graph replay
    }
}

extern "C" void kernel_launch(void* const* d_in, const int* in_sizes, int n_in,
                              void* d_out, int out_size) {
    const float* s = (const float*)d_in[0];
    const float* t = (const float*)d_in[1];
    const void* rows = d_in[2];
    const void* cols = d_in[3];
    int Ns = in_sizes[0] / KD;
    int Nt = in_sizes[1] / KD;
    int nb = in_sizes[2];
    int nmax = Ns > Nt ? Ns : Nt;

    dim3 tgrid((nmax + 31) / 32, KD / 32, 2);
    dim3 tblk(32, 8, 1);
    transpose_kernel<<<tgrid, tblk>>>(s, t, Ns, Nt);
    fused_kernel<<<TOTAL_BLOCKS, THREADS>>>(s, t, rows, cols,
                                            (float*)d_out, Ns, Nt, nb);
}

// round 4
// speedup vs baseline: 3.4222x; 1.0102x over previous
#include <cuda_runtime.h>

#define NRK 4
#define DW  64
#define KD  256          // NR*D plane stride
#define PAD 2048         // power-of-2 pad for bitonic (Nt <= 2048)
#define THREADS 256
#define PER 8            // sort elements per thread
#define NX  8            // search slots per thread (supports Ns <= 2048)
#define ALM_BLOCKS 8
#define NMAX 2048
#define TOTAL_BLOCKS (KD + ALM_BLOCKS)

// Static scratch (no allocation allowed)
__device__ float  g_sT[KD * NMAX];          // s transposed: [KD][Ns]
__device__ float  g_tT[KD * NMAX];          // t transposed: [KD][Nt]
__device__ double g_col[KD];                // per-column all-pairs partial
__device__ double g_almp[ALM_BLOCKS * NRK]; // per-block per-k anchor partials
__device__ int    g_count = 0;              // completion ticket (self-resetting)

// ---------------- tiled transpose: [N][256] -> [256][N] ----------------
__global__ void transpose_kernel(const float* __restrict__ s,
                                 const float* __restrict__ t,
                                 int Ns, int Nt) {
    __shared__ float tile[32][33];
    const float* src; float* dst; int N;
    if (blockIdx.z == 0) { src = s; dst = g_sT; N = Ns; }
    else                 { src = t; dst = g_tT; N = Nt; }
    const int tx = threadIdx.x, ty = threadIdx.y;  // 32 x 8
    const int r0 = blockIdx.x * 32, c0 = blockIdx.y * 32;
    #pragma unroll
    for (int i = 0; i < 4; i++) {
        int r = r0 + ty + i * 8;
        if (r < N) tile[ty + i * 8][tx] = src[r * KD + c0 + tx];
    }
    __syncthreads();
    #pragma unroll
    for (int i = 0; i < 4; i++) {
        int c  = c0 + ty + i * 8;   // KD-dim row of dst
        int rr = r0 + tx;           // N-dim col
        if (rr < N) dst[c * N + rr] = tile[tx][ty + i * 8];
    }
}

__device__ __forceinline__ void cmpswap(float& a, float& b, bool up) {
    float mn = fminf(a, b), mx = fmaxf(a, b);
    a = up ? mn : mx;
    b = up ? mx : mn;
}

// ---------------- fused: column pair-sums + ALM + finalize ----------------
__global__ void __launch_bounds__(THREADS) fused_kernel(
    const float* __restrict__ s, const float* __restrict__ t,
    const void* __restrict__ rows_raw, const void* __restrict__ cols_raw,
    float* __restrict__ out, int Ns, int Nt, int nb)
{
    __shared__ float  ysort[PAD];
    __shared__ float  ypre[PAD + 1];   // shifted: ypre[0]=0, ypre[i+1]=incl prefix i
    __shared__ float  fwarp[8];
    __shared__ double dwarp[8];
    __shared__ int    slast;

    const int tid  = threadIdx.x;
    const int lane = tid & 31;
    const int wid  = tid >> 5;
    const int b    = blockIdx.x;

    if (b >= KD) {
        // ======== ALM blocks: anchor-pair L1 sums, sliced over anchors ========
        __shared__ int is64;
        if (tid == 0) {
            const int* r32 = (const int*)rows_raw;
            is64 = (r32[1] == 0 && r32[3] == 0 && r32[5] == 0) ? 1 : 0;
        }
        __syncthreads();
        const int a = b - KD;
        const int chunk = (nb + ALM_BLOCKS - 1) / ALM_BLOCKS;
        const int lo = a * chunk, hi = min(nb, lo + chunk);
        const long long* r64 = (const long long*)rows_raw;
        const long long* c64 = (const long long*)cols_raw;
        const int* r32 = (const int*)rows_raw;
        const int* c32 = (const int*)cols_raw;
        double acc = 0.0;
        for (int bi = lo; bi < hi; bi++) {
            long long r = is64 ? r64[bi] : (long long)r32[bi];
            long long c = is64 ? c64[bi] : (long long)c32[bi];
            acc += (double)fabsf(s[r * KD + tid] - t[c * KD + tid]);
        }
        #pragma unroll
        for (int o = 16; o > 0; o >>= 1) acc += __shfl_down_sync(0xffffffffu, acc, o);
        if (lane == 0) dwarp[wid] = acc;
        __syncthreads();
        if (tid == 0) {
            #pragma unroll
            for (int k = 0; k < NRK; k++)
                g_almp[a * NRK + k] = dwarp[2 * k] + dwarp[2 * k + 1];
        }
    } else {
        // ======== column blocks: exact all-pairs L1 for plane coord b ========
        const float INF = __int_as_float(0x7f800000);
        const float* ycol = g_tT + (size_t)b * Nt;
        const float* xcol = g_sT + (size_t)b * Ns;
        const int base = tid * PER;

        float v[PER];
        #pragma unroll
        for (int m = 0; m < PER; m++)
            v[m] = (base + m < Nt) ? ycol[base + m] : INF;

        // --- phases k=2,4,8: sort own 8-chunk in registers ---
        {
            const bool asc = ((tid & 1) == 0);
            #pragma unroll
            for (int kk = 2; kk <= 8; kk <<= 1) {
                #pragma unroll
                for (int j = kk >> 1; j > 0; j >>= 1) {
                    #pragma unroll
                    for (int m = 0; m < PER; m++)
                        if ((m & j) == 0) {
                            bool up = (kk == 8) ? asc : ((m & kk) == 0);
                            cmpswap(v[m], v[m | j], up);
                        }
                }
            }
        }

        // --- phases k=16..2048: smem only for j>=256, shfl for j=128..8 ---
        float4* sh4 = (float4*)ysort;
        #pragma unroll
        for (int k = 16; k <= PAD; k <<= 1) {
            const bool up = ((tid & (k >> 3)) == 0);
            // cross-warp steps via smem (conflict-free float4)
            #pragma unroll
            for (int j = k >> 1; j >= 256; j >>= 1) {
                const int jd = j >> 3;
                sh4[tid * 2 + 0] = make_float4(v[0], v[1], v[2], v[3]);
                sh4[tid * 2 + 1] = make_float4(v[4], v[5], v[6], v[7]);
                __syncthreads();
                const int p = tid ^ jd;
                float4 oa = sh4[p * 2 + 0], ob = sh4[p * 2 + 1];
                float o[PER] = {oa.x, oa.y, oa.z, oa.w, ob.x, ob.y, ob.z, ob.w};
                const bool keep_min = (((tid & jd) == 0) == up);
                #pragma unroll
                for (int m = 0; m < PER; m++)
                    v[m] = keep_min ? fminf(v[m], o[m]) : fmaxf(v[m], o[m]);
                __syncthreads();
            }
            // intra-warp steps via shfl
            #pragma unroll
            for (int j = ((k >> 1) < 128 ? (k >> 1) : 128); j >= 8; j >>= 1) {
                const int jd = j >> 3;
                const bool keep_min = (((tid & jd) == 0) == up);
                #pragma unroll
                for (int m = 0; m < PER; m++) {
                    float o = __shfl_xor_sync(0xffffffffu, v[m], jd);
                    v[m] = keep_min ? fminf(v[m], o) : fmaxf(v[m], o);
                }
            }
            // intra-thread steps j=4,2,1
            #pragma unroll
            for (int j = 4; j > 0; j >>= 1) {
                #pragma unroll
                for (int m = 0; m < PER; m++)
                    if ((m & j) == 0) cmpswap(v[m], v[m | j], up);
            }
        }

        // --- inclusive prefix scan (pads -> 0), regs + shfl ---
        float pre[PER];
        {
            float run = 0.f;
            #pragma unroll
            for (int m = 0; m < PER; m++) {
                float x = (base + m < Nt) ? v[m] : 0.f;
                run += x;
                pre[m] = run;
            }
            float incl = run;
            #pragma unroll
            for (int o = 1; o < 32; o <<= 1) {
                float n = __shfl_up_sync(0xffffffffu, incl, o);
                if (lane >= o) incl += n;
            }
            if (lane == 31) fwarp[wid] = incl;
            const float excl = incl - run;
            __syncthreads();
            float woff = 0.f;
            #pragma unroll
            for (int w = 0; w < 8; w++)
                if (w < wid) woff += fwarp[w];
            const float off = woff + excl;
            #pragma unroll
            for (int m = 0; m < PER; m++) pre[m] += off;
        }

        // publish sorted values + shifted prefix sums to smem
        __syncthreads();  // ysort reuse safety
        sh4[tid * 2 + 0] = make_float4(v[0], v[1], v[2], v[3]);
        sh4[tid * 2 + 1] = make_float4(v[4], v[5], v[6], v[7]);
        #pragma unroll
        for (int m = 0; m < PER; m++) ypre[base + m + 1] = pre[m];
        if (tid == 0) ypre[0] = 0.f;
        __syncthreads();

        const float Ptot = ypre[Nt];

        // --- batched branchless binary search (8 independent chains) ---
        float x[NX];
        int   pos[NX];
        bool  act[NX];
        #pragma unroll
        for (int u = 0; u < NX; u++) {
            int i = tid + u * THREADS;
            act[u] = (i < Ns);
            x[u]   = act[u] ? xcol[i] : 0.f;
            pos[u] = 0;
        }
        #pragma unroll
        for (int step = PAD / 2; step >= 1; step >>= 1) {
            #pragma unroll
            for (int u = 0; u < NX; u++) {
                int c = pos[u] + step;
                float yv = ysort[c - 1];   // pads are +inf -> pos stays <= Nt
                if (yv <= x[u]) pos[u] = c;
            }
        }
        double acc = 0.0;
        #pragma unroll
        for (int u = 0; u < NX; u++) {
            float Pc = ypre[pos[u]];
            float contrib = x[u] * (float)(2 * pos[u] - Nt) + Ptot - 2.f * Pc;
            if (act[u]) acc += (double)contrib;
        }

        #pragma unroll
        for (int o = 16; o > 0; o >>= 1) acc += __shfl_down_sync(0xffffffffu, acc, o);
        if (lane == 0) dwarp[wid] = acc;
        __syncthreads();
        if (tid == 0) {
            double sum = 0.0;
            #pragma unroll
            for (int w = 0; w < 8; w++) sum += dwarp[w];
            g_col[b] = sum;
        }
    }

    // ======== completion ticket: last block finalizes ========
    if (tid == 0) {
        __threadfence();
        int tk = atomicAdd(&g_count, 1);
        slast = (tk == TOTAL_BLOCKS - 1) ? 1 : 0;
    }
    __syncthreads();
    if (!slast) return;
    __threadfence();

    // reduce g_col (256 doubles) by k-groups of 64
    double vv = g_col[tid];
    #pragma unroll
    for (int o = 16; o > 0; o >>= 1) vv += __shfl_down_sync(0xffffffffu, vv, o);
    if (lane == 0) dwarp[wid] = vv;
    __syncthreads();
    if (tid == 0) {
        const double params[NRK] = {0.4, 0.2, 0.2, 0.2};
        const double EPS = 3.0;
        const double nb_notB = (double)Ns * (double)Nt - (double)nb;
        double ret = 0.0;
        #pragma unroll
        for (int k = 0; k < NRK; k++) {
            double all = dwarp[2 * k] + dwarp[2 * k + 1];
            double alm = 0.0;
            #pragma unroll
            for (int a = 0; a < ALM_BLOCKS; a++) alm += g_almp[a * NRK + k];
            double notalm = all - alm;
            double lk = alm * nb_notB + (EPS * nb_notB - notalm) * (double)nb;
            ret += params[k] * lk / (double)DW;
        }
        out[0] = (float)(ret / ((double)Ns * (double)Nt));
        g_count = 0;  // reset for next graph replay
    }
}

extern "C" void kernel_launch(void* const* d_in, const int* in_sizes, int n_in,
                              void* d_out, int out_size) {
    const float* s = (const float*)d_in[0];
    const float* t = (const float*)d_in[1];
    const void* rows = d_in[2];
    const void* cols = d_in[3];
    int Ns = in_sizes[0] / KD;
    int Nt = in_sizes[1] / KD;
    int nb = in_sizes[2];
    int nmax = Ns > Nt ? Ns : Nt;

    dim3 tgrid((nmax + 31) / 32, KD / 32, 2);
    dim3 tblk(32, 8, 1);
    transpose_kernel<<<tgrid, tblk>>>(s, t, Ns, Nt);
    fused_kernel<<<TOTAL_BLOCKS, THREADS>>>(s, t, rows, cols,
                                            (float*)d_out, Ns, Nt, nb);
}